// round 4
// baseline (speedup 1.0000x reference)
#include <cuda_runtime.h>

#define FM_H 120
#define FM_W 120
#define FM_C 64
#define FM_HW (FM_H * FM_W)
#define N_BOX 4096

typedef unsigned long long ull;

// ---------------- device scratch (no allocations allowed) ----------------
__device__ float g_fmT[FM_HW * FM_C];          // [H*W][C]  3.69 MB
__device__ float g_pooled[N_BOX * 3 * 64];     // [n][scale3|scale7|scale11] == concat[n][192]
__device__ float g_gvec[64];                   // global avg pool
__device__ __align__(16) float g_pb1eff[128];  // pb1 + gh @ p1[192:256]

// ---------------- f32x2 packed helpers ----------------
__device__ __forceinline__ void ffma2(ull& d, ull a, ull b) {
    asm("fma.rn.f32x2 %0, %1, %2, %0;" : "+l"(d) : "l"(a), "l"(b));
}
__device__ __forceinline__ ull bcast2(float x) {
    ull r; asm("mov.b64 %0, {%1, %1};" : "=l"(r) : "f"(x)); return r;
}
__device__ __forceinline__ ull mk2(float x, float y) {
    ull r; asm("mov.b64 %0, {%1, %2};" : "=l"(r) : "f"(x), "f"(y)); return r;
}
__device__ __forceinline__ float2 un2(ull v) {
    float2 f; asm("mov.b64 {%0, %1}, %2;" : "=f"(f.x), "=f"(f.y) : "l"(v)); return f;
}
__device__ __forceinline__ ull relu2(ull v) {
    float2 f = un2(v);
    return mk2(fmaxf(f.x, 0.f), fmaxf(f.y, 0.f));
}

__device__ __forceinline__ float4 half_reduce(float4 a) {
    a.x += __shfl_down_sync(0xffffffffu, a.x, 16);
    a.y += __shfl_down_sync(0xffffffffu, a.y, 16);
    a.z += __shfl_down_sync(0xffffffffu, a.z, 16);
    a.w += __shfl_down_sync(0xffffffffu, a.w, 16);
    return a;
}

// ---------------- kernel 1: transpose [C,H,W]->[H*W,C]  +  global mean ----------------
__global__ void k_prep(const float* __restrict__ fm) {
    if (blockIdx.x < FM_HW / 64) {
        __shared__ float tile[64 * 65];
        const int p0 = blockIdx.x * 64;
        const int t = threadIdx.x;
#pragma unroll
        for (int i = 0; i < 16; i++) {
            int idx = i * 256 + t;
            int c = idx >> 6, p = idx & 63;
            tile[p * 65 + c] = fm[c * FM_HW + p0 + p];
        }
        __syncthreads();
#pragma unroll
        for (int i = 0; i < 16; i++) {
            int idx = i * 256 + t;
            int p = idx >> 6, c = idx & 63;
            g_fmT[(p0 + p) * 64 + c] = tile[p * 65 + c];
        }
    } else {
        __shared__ float red[256];
        const int c = blockIdx.x - FM_HW / 64;
        float s = 0.f;
        for (int p = threadIdx.x; p < FM_HW; p += 256) s += fm[c * FM_HW + p];
        red[threadIdx.x] = s;
        __syncthreads();
        for (int st = 128; st > 0; st >>= 1) {
            if (threadIdx.x < st) red[threadIdx.x] += red[threadIdx.x + st];
            __syncthreads();
        }
        if (threadIdx.x == 0) g_gvec[c] = red[0] * (1.0f / (float)FM_HW);
    }
}

// ---------------- kernel 2: shared head on g, fold into pb1eff ----------------
__global__ void k_headg(const float* __restrict__ w1, const float* __restrict__ b1,
                        const float* __restrict__ w2, const float* __restrict__ b2,
                        const float* __restrict__ p1, const float* __restrict__ pb1) {
    __shared__ float h1[128];
    __shared__ float gh[64];
    const int t = threadIdx.x;  // 128 threads
    {
        float acc = b1[t];
#pragma unroll 8
        for (int c = 0; c < 64; c++) acc += g_gvec[c] * w1[c * 128 + t];
        h1[t] = fmaxf(acc, 0.f);
    }
    __syncthreads();
    if (t < 64) {
        float acc = b2[t];
#pragma unroll 8
        for (int k = 0; k < 128; k++) acc += h1[k] * w2[k * 64 + t];
        gh[t] = fmaxf(acc, 0.f);
    }
    __syncthreads();
    {
        float acc = pb1[t];
#pragma unroll 8
        for (int j = 0; j < 64; j++) acc += gh[j] * p1[(192 + j) * 128 + t];
        g_pb1eff[t] = acc;
    }
}

// ---------------- kernel 3: ROI pooling (unchanged from R3 passing version) ----------------
template <int R>
__device__ __forceinline__ float4 accum_scale(const float4* __restrict__ base4,
                                              float Ax, float Sx, float Ay, float Sy,
                                              int j0, int j1, int half, int lane4) {
    const float invR = 1.0f / (float)R;
    float4 acc = make_float4(0.f, 0.f, 0.f, 0.f);
    const int steps = ((j1 - j0) + 1) >> 1;
#pragma unroll 4
    for (int i = 0; i < steps; i++) {
        int j = j0 + 2 * i + half;
        float valid = (j < j1) ? 1.f : 0.f;
        int jc = min(j, j1 - 1);
        int row = jc / R;
        int col = jc - row * R;
        float iy = Ay + Sy * ((2.0f * row + 1.0f) * invR - 1.0f);
        float ix = Ax + Sx * ((2.0f * col + 1.0f) * invR - 1.0f);
        float y0f = floorf(iy), x0f = floorf(ix);
        float wy = iy - y0f, wx = ix - x0f;
        int y0 = (int)y0f, x0 = (int)x0f;
        float vy0 = (y0 >= 0 && y0 < FM_H) ? 1.f : 0.f;
        float vy1 = (y0 >= -1 && y0 < FM_H - 1) ? 1.f : 0.f;
        float vx0 = (x0 >= 0 && x0 < FM_W) ? 1.f : 0.f;
        float vx1 = (x0 >= -1 && x0 < FM_W - 1) ? 1.f : 0.f;
        int y0c = min(max(y0, 0), FM_H - 1);
        int y1c = min(max(y0 + 1, 0), FM_H - 1);
        int x0c = min(max(x0, 0), FM_W - 1);
        int x1c = min(max(x0 + 1, 0), FM_W - 1);
        float wy0 = (1.f - wy) * vy0 * valid;
        float wy1 = wy * vy1 * valid;
        float w00 = (1.f - wx) * vx0 * wy0;
        float w10 = wx * vx1 * wy0;
        float w01 = (1.f - wx) * vx0 * wy1;
        float w11 = wx * vx1 * wy1;
        const float4* r0 = base4 + y0c * (FM_W * 16) + lane4;
        const float4* r1 = base4 + y1c * (FM_W * 16) + lane4;
        float4 v00 = __ldg(r0 + x0c * 16);
        float4 v10 = __ldg(r0 + x1c * 16);
        float4 v01 = __ldg(r1 + x0c * 16);
        float4 v11 = __ldg(r1 + x1c * 16);
        acc.x += w00 * v00.x + w10 * v10.x + w01 * v01.x + w11 * v11.x;
        acc.y += w00 * v00.y + w10 * v10.y + w01 * v01.y + w11 * v11.y;
        acc.z += w00 * v00.z + w10 * v10.z + w01 * v01.z + w11 * v11.z;
        acc.w += w00 * v00.w + w10 * v10.w + w01 * v01.w + w11 * v11.w;
    }
    return acc;
}

__global__ void __launch_bounds__(256) k_pool(const float* __restrict__ boxes) {
    __shared__ float4 s11[4][16];
    const int w = threadIdx.x >> 5;
    const int lane = threadIdx.x & 31;
    const int boxL = w >> 1;
    const int role = w & 1;
    const int half = lane >> 4;
    const int lane4 = lane & 15;
    const int box = blockIdx.x * 4 + boxL;

    const float4 b = __ldg(reinterpret_cast<const float4*>(boxes) + box);
    const float sc = 2.0f / 960.0f;
    float x1 = b.x * sc - 1.f, y1 = b.y * sc - 1.f;
    float x2 = b.z * sc - 1.f, y2 = b.w * sc - 1.f;
    float cx = 0.5f * (x1 + x2), cy = 0.5f * (y1 + y2);
    float bw = fmaxf(x2 - x1, 1e-6f), bh = fmaxf(y2 - y1, 1e-6f);
    float Ax = 0.5f * ((cx + 1.f) * (float)FM_W - 1.f);
    float Ay = 0.5f * ((cy + 1.f) * (float)FM_H - 1.f);
    float Sx = bw * (0.25f * (float)FM_W);
    float Sy = bh * (0.25f * (float)FM_H);

    const float4* base4 = reinterpret_cast<const float4*>(g_fmT);
    float4 a11;

    if (role == 0) {
        float4 a7 = accum_scale<7>(base4, Ax, Sx, Ay, Sy, 0, 49, half, lane4);
        a11 = accum_scale<11>(base4, Ax, Sx, Ay, Sy, 0, 44, half, lane4);
        a7 = half_reduce(a7);
        a11 = half_reduce(a11);
        if (lane < 16) {
            s11[boxL][lane4] = a11;
            const float s7 = (1.0f / 7.0f) * (1.0f / 7.0f);
            float4 o = make_float4(a7.x * s7, a7.y * s7, a7.z * s7, a7.w * s7);
            reinterpret_cast<float4*>(g_pooled + box * 192 + 64)[lane4] = o;
        }
    } else {
        float4 a3 = accum_scale<3>(base4, Ax, Sx, Ay, Sy, 0, 9, half, lane4);
        a11 = accum_scale<11>(base4, Ax, Sx, Ay, Sy, 44, 121, half, lane4);
        a3 = half_reduce(a3);
        a11 = half_reduce(a11);
        if (lane < 16) {
            const float s3 = (1.0f / 3.0f) * (1.0f / 3.0f);
            float4 o = make_float4(a3.x * s3, a3.y * s3, a3.z * s3, a3.w * s3);
            reinterpret_cast<float4*>(g_pooled + box * 192)[lane4] = o;
        }
    }
    __syncthreads();
    if (role == 1 && lane < 16) {
        float4 p = s11[boxL][lane4];
        const float s11c = (1.0f / 11.0f) * (1.0f / 11.0f);
        float4 o = make_float4((p.x + a11.x) * s11c, (p.y + a11.y) * s11c,
                               (p.z + a11.z) * s11c, (p.w + a11.w) * s11c);
        reinterpret_cast<float4*>(g_pooled + box * 192 + 128)[lane4] = o;
    }
}

// ---------------- kernel 4: fused MLP, f32x2 row-pair packed ----------------
// 16 boxes/block, 256 threads, grid 256.
// sA: 3072 floats = X2[24 pairs][64 k] float2, later F2[8 boxpairs][192] float2
// sB: 6144 floats = H2[24 pairs][128] float2, later h2[8 boxpairs][128] float2
__global__ void __launch_bounds__(256) k_mlp(const float* __restrict__ w1, const float* __restrict__ b1,
                                             const float* __restrict__ w2, const float* __restrict__ b2,
                                             const float* __restrict__ p1, const float* __restrict__ p2,
                                             const float* __restrict__ pb2, float* __restrict__ out) {
    __shared__ __align__(16) float sA[3072];
    __shared__ __align__(16) float sB[6144];
    const int t = threadIdx.x;
    const int pg = t >> 5;   // 8 groups
    const int cg = t & 31;   // 32 col groups

    // phase 0: load pooled -> pair-interleaved X2
    {
        const float* src = g_pooled + blockIdx.x * (16 * 192);
        for (int idx = t; idx < 3072; idx += 256) {
            int row = idx >> 6, k = idx & 63;
            sA[((row >> 1) * 64 + k) * 2 + (row & 1)] = src[idx];
        }
    }
    __syncthreads();

    // phase 1: H2[24][128] = relu(X @ w1 + b1); pairs pg*3+pp, cols 4cg..4cg+3
    {
        ull acc[3][4];
        float4 bv = __ldg(reinterpret_cast<const float4*>(b1) + cg);
        {
            ull c0 = bcast2(bv.x), c1 = bcast2(bv.y), c2 = bcast2(bv.z), c3 = bcast2(bv.w);
#pragma unroll
            for (int pp = 0; pp < 3; pp++) { acc[pp][0] = c0; acc[pp][1] = c1; acc[pp][2] = c2; acc[pp][3] = c3; }
        }
        const float4* w1r = reinterpret_cast<const float4*>(w1) + cg;
#pragma unroll 4
        for (int k = 0; k < 64; k += 2) {
            ulonglong2 a0 = *reinterpret_cast<const ulonglong2*>(&sA[((pg * 3 + 0) * 64 + k) * 2]);
            ulonglong2 a1 = *reinterpret_cast<const ulonglong2*>(&sA[((pg * 3 + 1) * 64 + k) * 2]);
            ulonglong2 a2 = *reinterpret_cast<const ulonglong2*>(&sA[((pg * 3 + 2) * 64 + k) * 2]);
            float4 wv0 = __ldg(w1r + k * 32);
            float4 wv1 = __ldg(w1r + (k + 1) * 32);
            ull w00 = bcast2(wv0.x), w01 = bcast2(wv0.y), w02 = bcast2(wv0.z), w03 = bcast2(wv0.w);
            ull w10 = bcast2(wv1.x), w11 = bcast2(wv1.y), w12 = bcast2(wv1.z), w13 = bcast2(wv1.w);
            ffma2(acc[0][0], a0.x, w00); ffma2(acc[0][1], a0.x, w01); ffma2(acc[0][2], a0.x, w02); ffma2(acc[0][3], a0.x, w03);
            ffma2(acc[1][0], a1.x, w00); ffma2(acc[1][1], a1.x, w01); ffma2(acc[1][2], a1.x, w02); ffma2(acc[1][3], a1.x, w03);
            ffma2(acc[2][0], a2.x, w00); ffma2(acc[2][1], a2.x, w01); ffma2(acc[2][2], a2.x, w02); ffma2(acc[2][3], a2.x, w03);
            ffma2(acc[0][0], a0.y, w10); ffma2(acc[0][1], a0.y, w11); ffma2(acc[0][2], a0.y, w12); ffma2(acc[0][3], a0.y, w13);
            ffma2(acc[1][0], a1.y, w10); ffma2(acc[1][1], a1.y, w11); ffma2(acc[1][2], a1.y, w12); ffma2(acc[1][3], a1.y, w13);
            ffma2(acc[2][0], a2.y, w10); ffma2(acc[2][1], a2.y, w11); ffma2(acc[2][2], a2.y, w12); ffma2(acc[2][3], a2.y, w13);
        }
#pragma unroll
        for (int pp = 0; pp < 3; pp++) {
            ulonglong2 s0, s1;
            s0.x = relu2(acc[pp][0]); s0.y = relu2(acc[pp][1]);
            s1.x = relu2(acc[pp][2]); s1.y = relu2(acc[pp][3]);
            *reinterpret_cast<ulonglong2*>(&sB[((pg * 3 + pp) * 128 + 4 * cg) * 2]) = s0;
            *reinterpret_cast<ulonglong2*>(&sB[((pg * 3 + pp) * 128 + 4 * cg + 2) * 2]) = s1;
        }
    }
    __syncthreads();

    // phase 2: feats = relu(H @ w2 + b2) -> F2 (concat layout, box-pair interleaved) in sA
    {
        ull acc[3][2];
        float2 bv = __ldg(reinterpret_cast<const float2*>(b2) + cg);
        {
            ull c0 = bcast2(bv.x), c1 = bcast2(bv.y);
#pragma unroll
            for (int pp = 0; pp < 3; pp++) { acc[pp][0] = c0; acc[pp][1] = c1; }
        }
        const float2* w2r = reinterpret_cast<const float2*>(w2) + cg;
#pragma unroll 4
        for (int k = 0; k < 128; k += 2) {
            ulonglong2 a0 = *reinterpret_cast<const ulonglong2*>(&sB[((pg * 3 + 0) * 128 + k) * 2]);
            ulonglong2 a1 = *reinterpret_cast<const ulonglong2*>(&sB[((pg * 3 + 1) * 128 + k) * 2]);
            ulonglong2 a2 = *reinterpret_cast<const ulonglong2*>(&sB[((pg * 3 + 2) * 128 + k) * 2]);
            float2 wv0 = __ldg(w2r + k * 32);
            float2 wv1 = __ldg(w2r + (k + 1) * 32);
            ull w00 = bcast2(wv0.x), w01 = bcast2(wv0.y);
            ull w10 = bcast2(wv1.x), w11 = bcast2(wv1.y);
            ffma2(acc[0][0], a0.x, w00); ffma2(acc[0][1], a0.x, w01);
            ffma2(acc[1][0], a1.x, w00); ffma2(acc[1][1], a1.x, w01);
            ffma2(acc[2][0], a2.x, w00); ffma2(acc[2][1], a2.x, w01);
            ffma2(acc[0][0], a0.y, w10); ffma2(acc[0][1], a0.y, w11);
            ffma2(acc[1][0], a1.y, w10); ffma2(acc[1][1], a1.y, w11);
            ffma2(acc[2][0], a2.y, w10); ffma2(acc[2][1], a2.y, w11);
        }
        __syncthreads();
#pragma unroll
        for (int pp = 0; pp < 3; pp++) {
            int r0 = 2 * (pg * 3 + pp);
            int r1 = r0 + 1;
            int box0 = r0 / 3, s0 = r0 - box0 * 3;
            int box1 = r1 / 3, s1 = r1 - box1 * 3;
#pragma unroll
            for (int c = 0; c < 2; c++) {
                float2 f = un2(acc[pp][c]);
                int col = 2 * cg + c;
                sA[((box0 >> 1) * 192 + s0 * 64 + col) * 2 + (box0 & 1)] = fmaxf(f.x, 0.f);
                sA[((box1 >> 1) * 192 + s1 * 64 + col) * 2 + (box1 & 1)] = fmaxf(f.y, 0.f);
            }
        }
    }
    __syncthreads();

    // phase 3: h2[8 boxpairs][128] = relu(concat @ p1[0:192] + pb1eff) -> sB
    {
        ull acc[4];
        float4 bv = __ldg(reinterpret_cast<const float4*>(g_pb1eff) + cg);
        acc[0] = bcast2(bv.x); acc[1] = bcast2(bv.y); acc[2] = bcast2(bv.z); acc[3] = bcast2(bv.w);
        const float4* p1r = reinterpret_cast<const float4*>(p1) + cg;
#pragma unroll 4
        for (int k = 0; k < 192; k += 2) {
            ulonglong2 a = *reinterpret_cast<const ulonglong2*>(&sA[(pg * 192 + k) * 2]);
            float4 wv0 = __ldg(p1r + k * 32);
            float4 wv1 = __ldg(p1r + (k + 1) * 32);
            ffma2(acc[0], a.x, bcast2(wv0.x)); ffma2(acc[1], a.x, bcast2(wv0.y));
            ffma2(acc[2], a.x, bcast2(wv0.z)); ffma2(acc[3], a.x, bcast2(wv0.w));
            ffma2(acc[0], a.y, bcast2(wv1.x)); ffma2(acc[1], a.y, bcast2(wv1.y));
            ffma2(acc[2], a.y, bcast2(wv1.z)); ffma2(acc[3], a.y, bcast2(wv1.w));
        }
        ulonglong2 s0, s1;
        s0.x = relu2(acc[0]); s0.y = relu2(acc[1]);
        s1.x = relu2(acc[2]); s1.y = relu2(acc[3]);
        *reinterpret_cast<ulonglong2*>(&sB[(pg * 128 + 4 * cg) * 2]) = s0;
        *reinterpret_cast<ulonglong2*>(&sB[(pg * 128 + 4 * cg + 2) * 2]) = s1;
    }
    __syncthreads();

    // phase 4: out = relu(h2 @ p2 + pb2)
    {
        ull acc[2];
        float2 bv = __ldg(reinterpret_cast<const float2*>(pb2) + cg);
        acc[0] = bcast2(bv.x); acc[1] = bcast2(bv.y);
        const float2* p2r = reinterpret_cast<const float2*>(p2) + cg;
#pragma unroll 4
        for (int k = 0; k < 128; k += 2) {
            ulonglong2 a = *reinterpret_cast<const ulonglong2*>(&sB[(pg * 128 + k) * 2]);
            float2 wv0 = __ldg(p2r + k * 32);
            float2 wv1 = __ldg(p2r + (k + 1) * 32);
            ffma2(acc[0], a.x, bcast2(wv0.x)); ffma2(acc[1], a.x, bcast2(wv0.y));
            ffma2(acc[0], a.y, bcast2(wv1.x)); ffma2(acc[1], a.y, bcast2(wv1.y));
        }
        float2 f0 = un2(acc[0]);
        float2 f1 = un2(acc[1]);
        int boxg = blockIdx.x * 16 + 2 * pg;
        *reinterpret_cast<float2*>(&out[boxg * 64 + 2 * cg]) =
            make_float2(fmaxf(f0.x, 0.f), fmaxf(f1.x, 0.f));
        *reinterpret_cast<float2*>(&out[(boxg + 1) * 64 + 2 * cg]) =
            make_float2(fmaxf(f0.y, 0.f), fmaxf(f1.y, 0.f));
    }
}

// ---------------- launch ----------------
extern "C" void kernel_launch(void* const* d_in, const int* in_sizes, int n_in,
                              void* d_out, int out_size) {
    const float* fm    = (const float*)d_in[0];
    const float* boxes = (const float*)d_in[1];
    const float* w1    = (const float*)d_in[2];
    const float* b1    = (const float*)d_in[3];
    const float* w2    = (const float*)d_in[4];
    const float* b2    = (const float*)d_in[5];
    const float* p1    = (const float*)d_in[6];
    const float* pb1   = (const float*)d_in[7];
    const float* p2    = (const float*)d_in[8];
    const float* pb2   = (const float*)d_in[9];
    float* out = (float*)d_out;

    k_prep<<<FM_HW / 64 + 64, 256>>>(fm);
    k_headg<<<1, 128>>>(w1, b1, w2, b2, p1, pb1);
    k_pool<<<N_BOX / 4, 256>>>(boxes);
    k_mlp<<<N_BOX / 16, 256>>>(w1, b1, w2, b2, p1, p2, pb2, out);
}